// round 1
// baseline (speedup 1.0000x reference)
#include <cuda_runtime.h>
#include <math.h>
#include <float.h>

// ---------------- Scratch (device globals; no allocation allowed) ----------------
__device__ float g_ps[25600 * 196];     // ps_map [160*160][196]
__device__ float g_bb[25600 * 196];     // bb_map [160*160][196]
__device__ float g_off[300 * 4];        // offsets from part2_2(rois)
__device__ float g_roisall[600 * 5];    // rois_all
__device__ float g_scores[600];         // cls_score per roi

// ---------------- GEMM: C[25600 x 392] = feat @ [W_ps | W_bb] + bias -------------
// BM=128, BN=56, BK=16, 256 threads, micro-tile 4 rows x 7 cols.
__global__ __launch_bounds__(256) void gemm_maps(
    const float* __restrict__ A,      // [25600][1024]
    const float* __restrict__ Wps,    // [1024][196]
    const float* __restrict__ bps,    // [196]
    const float* __restrict__ Wbb,    // [1024][196]
    const float* __restrict__ bbb,    // [196]
    float* __restrict__ Cps,          // [25600][196]
    float* __restrict__ Cbb)          // [25600][196]
{
    __shared__ float As[16][128];
    __shared__ float Bs[16][56];

    const int tid = threadIdx.x;
    const int rowBase = blockIdx.x * 128;
    const int colBase = blockIdx.y * 56;
    const int trow = tid >> 3;     // 0..31
    const int tcol = tid & 7;      // 0..7
    const int m0 = trow * 4;
    const int n0 = tcol * 7;

    float acc[4][7];
#pragma unroll
    for (int u = 0; u < 4; u++)
#pragma unroll
        for (int q = 0; q < 7; q++) acc[u][q] = 0.0f;

    for (int kt = 0; kt < 64; ++kt) {
        const int kb = kt * 16;

        // global -> regs
        float4 av[2];
#pragma unroll
        for (int i = 0; i < 2; i++) {
            int slot = tid + i * 256;          // 0..511
            int ar = slot >> 2;                // row in tile
            int kq = slot & 3;                 // which float4 of the 16-k chunk
            av[i] = *reinterpret_cast<const float4*>(
                &A[(size_t)(rowBase + ar) * 1024 + kb + kq * 4]);
        }
        float bv[4];
        int bk[4], bn[4];
#pragma unroll
        for (int i = 0; i < 4; i++) {
            int idx = tid + i * 256;           // 0..1023, valid < 896
            if (idx < 896) {
                int k = idx / 56, n = idx % 56;
                int c = colBase + n;
                bv[i] = (c < 196) ? Wps[(size_t)(kb + k) * 196 + c]
                                  : Wbb[(size_t)(kb + k) * 196 + (c - 196)];
                bk[i] = k; bn[i] = n;
            } else {
                bk[i] = -1; bn[i] = 0; bv[i] = 0.0f;
            }
        }

        __syncthreads();   // previous compute done before overwriting smem

        // regs -> smem (A transposed to [k][m])
#pragma unroll
        for (int i = 0; i < 2; i++) {
            int slot = tid + i * 256;
            int ar = slot >> 2;
            int kq = slot & 3;
            As[kq * 4 + 0][ar] = av[i].x;
            As[kq * 4 + 1][ar] = av[i].y;
            As[kq * 4 + 2][ar] = av[i].z;
            As[kq * 4 + 3][ar] = av[i].w;
        }
#pragma unroll
        for (int i = 0; i < 4; i++)
            if (bk[i] >= 0) Bs[bk[i]][bn[i]] = bv[i];

        __syncthreads();

#pragma unroll
        for (int k = 0; k < 16; k++) {
            float4 a = *reinterpret_cast<const float4*>(&As[k][m0]);
#pragma unroll
            for (int q = 0; q < 7; q++) {
                float b = Bs[k][n0 + q];
                acc[0][q] = fmaf(a.x, b, acc[0][q]);
                acc[1][q] = fmaf(a.y, b, acc[1][q]);
                acc[2][q] = fmaf(a.z, b, acc[2][q]);
                acc[3][q] = fmaf(a.w, b, acc[3][q]);
            }
        }
    }

    // epilogue: bias + store
#pragma unroll
    for (int q = 0; q < 7; q++) {
        int c = colBase + n0 + q;
        float bias;
        float* Cout;
        int cc;
        if (c < 196) { bias = bps[c]; Cout = Cps; cc = c; }
        else         { bias = bbb[c - 196]; Cout = Cbb; cc = c - 196; }
#pragma unroll
        for (int u = 0; u < 4; u++) {
            Cout[(size_t)(rowBase + m0 + u) * 196 + cc] = acc[u][q] + bias;
        }
    }
}

// ---------------- Bilinear PS-ROI sample: 4 channels p*49 + i*7 + j --------------
__device__ __forceinline__ void ps_sample4(const float* __restrict__ map,
                                           float y, float x, int cbase, float v[4])
{
    float y0f = floorf(y), x0f = floorf(x);
    float wy = y - y0f, wx = x - x0f;
    int y0 = (int)y0f; y0 = min(max(y0, 0), 159);
    int y1c = min(y0 + 1, 159);
    int x0 = (int)x0f; x0 = min(max(x0, 0), 159);
    int x1c = min(x0 + 1, 159);

    const float* p00 = map + (size_t)(y0 * 160 + x0) * 196 + cbase;
    const float* p01 = map + (size_t)(y0 * 160 + x1c) * 196 + cbase;
    const float* p10 = map + (size_t)(y1c * 160 + x0) * 196 + cbase;
    const float* p11 = map + (size_t)(y1c * 160 + x1c) * 196 + cbase;

    float w00 = (1.0f - wy) * (1.0f - wx);
    float w01 = (1.0f - wy) * wx;
    float w10 = wy * (1.0f - wx);
    float w11 = wy * wx;
#pragma unroll
    for (int p = 0; p < 4; p++) {
        v[p] = p00[p * 49] * w00 + p01[p * 49] * w01 +
               p10[p * 49] * w10 + p11[p * 49] * w11;
    }
}

// ---------------- part2_2: pooled 4-vector per roi -------------------------------
__global__ __launch_bounds__(256) void pooled4_kernel(
    const float* __restrict__ rois,   // [n][5]
    const float* __restrict__ map,    // [25600][196]
    float* __restrict__ out)          // [n][4]
{
    int r = blockIdx.x;
    const float* roi = rois + (size_t)r * 5;
    float x1 = roi[1] * 0.125f;
    float yy1 = roi[2] * 0.125f;
    float x2 = roi[3] * 0.125f;
    float y2 = roi[4] * 0.125f;
    float bw = __fdiv_rn(x2 - x1, 7.0f);
    float bh = __fdiv_rn(y2 - yy1, 7.0f);

    int t = threadIdx.x;
    float v[4] = {0.f, 0.f, 0.f, 0.f};
    if (t < 196) {
        int yI = t / 14, xI = t % 14;
        int i = yI >> 1, sy = yI & 1;
        int j = xI >> 1, sx = xI & 1;
        float y = __fmaf_rn((float)i + (sy ? 0.75f : 0.25f), bh, yy1);
        float x = __fmaf_rn((float)j + (sx ? 0.75f : 0.25f), bw, x1);
        ps_sample4(map, y, x, i * 7 + j, v);
    }

    __shared__ float red[4][256];
#pragma unroll
    for (int p = 0; p < 4; p++) red[p][t] = v[p];
    __syncthreads();
    for (int s = 128; s > 0; s >>= 1) {
        if (t < s) {
#pragma unroll
            for (int p = 0; p < 4; p++) red[p][t] += red[p][t + s];
        }
        __syncthreads();
    }
    if (t < 4) out[(size_t)r * 4 + t] = __fdiv_rn(red[t][0], 196.0f);
}

// ---------------- proposals: bbox_transform_inv + clip + assemble rois_all -------
__global__ void proposal_kernel(const float* __restrict__ rois,   // [300][5]
                                const float* __restrict__ off,    // [300][4]
                                float* __restrict__ roisall,      // [600][5]
                                float* __restrict__ out_roisall)  // d_out section
{
    int r = blockIdx.x * blockDim.x + threadIdx.x;
    if (r >= 300) return;

#pragma unroll
    for (int c = 0; c < 5; c++) {
        float val = rois[(size_t)r * 5 + c];
        roisall[(size_t)r * 5 + c] = val;
        out_roisall[(size_t)r * 5 + c] = val;
    }

    float x1 = rois[r * 5 + 1], y1 = rois[r * 5 + 2];
    float x2 = rois[r * 5 + 3], y2 = rois[r * 5 + 4];
    float w = x2 - x1 + 1.0f, h = y2 - y1 + 1.0f;
    float cx = x1 + 0.5f * w, cy = y1 + 0.5f * h;
    float dx = off[r * 4 + 0], dy = off[r * 4 + 1];
    float dw = off[r * 4 + 2], dh = off[r * 4 + 3];
    float pcx = dx * w + cx, pcy = dy * h + cy;
    // double-precision exp then round to fp32: <=0.5 ulp, matches XLA within ~1 ulp
    float edw = (float)exp((double)dw);
    float edh = (float)exp((double)dh);
    float pw = edw * w, ph = edh * h;
    float px1 = pcx - 0.5f * pw, py1 = pcy - 0.5f * ph;
    float px2 = pcx + 0.5f * pw, py2 = pcy + 0.5f * ph;
    px1 = fminf(fmaxf(px1, 0.0f), 1279.0f);
    py1 = fminf(fmaxf(py1, 0.0f), 1279.0f);
    px2 = fminf(fmaxf(px2, 0.0f), 1279.0f);
    py2 = fminf(fmaxf(py2, 0.0f), 1279.0f);

    int rr = 300 + r;
    float vals[5] = {0.0f, px1, py1, px2, py2};
#pragma unroll
    for (int c = 0; c < 5; c++) {
        roisall[(size_t)rr * 5 + c] = vals[c];
        out_roisall[(size_t)rr * 5 + c] = vals[c];
    }
}

// ---------------- part2_1: cls / cls_result / cls_score / mask_result ------------
__global__ __launch_bounds__(256) void cls_mask_kernel(
    const float* __restrict__ roisall,  // [600][5]
    const float* __restrict__ psmap,    // [25600][196]
    float* __restrict__ out_cls,        // [600][2]
    float* __restrict__ out_res,        // [600]
    float* __restrict__ out_score,      // [600]
    float* __restrict__ out_mask,       // [600][14][14][2]
    float* __restrict__ scores)         // [600]
{
    int r = blockIdx.x;
    const float* roi = roisall + (size_t)r * 5;
    float x1 = roi[1] * 0.125f;
    float yy1 = roi[2] * 0.125f;
    float x2 = roi[3] * 0.125f;
    float y2 = roi[4] * 0.125f;
    float bw = __fdiv_rn(x2 - x1, 7.0f);
    float bh = __fdiv_rn(y2 - yy1, 7.0f);

    int t = threadIdx.x;
    float v[4] = {0.f, 0.f, 0.f, 0.f};
    float cm0 = 0.f, cm1 = 0.f;
    if (t < 196) {
        int yI = t / 14, xI = t % 14;
        int i = yI >> 1, sy = yI & 1;
        int j = xI >> 1, sx = xI & 1;
        float y = __fmaf_rn((float)i + (sy ? 0.75f : 0.25f), bh, yy1);
        float x = __fmaf_rn((float)j + (sx ? 0.75f : 0.25f), bw, x1);
        ps_sample4(psmap, y, x, i * 7 + j, v);
        cm0 = fmaxf(v[0], v[2]);   // copy 0: classes v[0], v[2]
        cm1 = fmaxf(v[1], v[3]);   // copy 1: classes v[1], v[3]
    }

    __shared__ float red[2][256];
    __shared__ int s_res;
    red[0][t] = cm0;
    red[1][t] = cm1;
    __syncthreads();
    for (int s = 128; s > 0; s >>= 1) {
        if (t < s) {
            red[0][t] += red[0][t + s];
            red[1][t] += red[1][t + s];
        }
        __syncthreads();
    }
    if (t == 0) {
        float a0 = __fdiv_rn(red[0][0], 196.0f);
        float a1 = __fdiv_rn(red[1][0], 196.0f);
        double m = (a0 > a1) ? (double)a0 : (double)a1;
        double e0 = exp((double)a0 - m);
        double e1 = exp((double)a1 - m);
        double inv = 1.0 / (e0 + e1);
        float c0 = (float)(e0 * inv);
        float c1 = (float)(e1 * inv);
        int res = (c1 > c0) ? 1 : 0;
        float sc = fmaxf(c0, c1);
        out_cls[(size_t)r * 2 + 0] = c0;
        out_cls[(size_t)r * 2 + 1] = c1;
        out_res[r] = (float)res;
        out_score[r] = sc;
        scores[r] = sc;
        s_res = res;
    }
    __syncthreads();

    if (t < 196) {
        int copy = s_res;
        float m0 = v[copy], m1 = v[2 + copy];
        float mm = fmaxf(m0, m1);
        float e0 = expf(m0 - mm);
        float e1 = expf(m1 - mm);
        float s = e0 + e1;
        out_mask[(size_t)r * 392 + t * 2 + 0] = __fdiv_rn(e0, s);
        out_mask[(size_t)r * 392 + t * 2 + 1] = __fdiv_rn(e1, s);
    }
}

// ---------------- NMS (single block, 640 threads) --------------------------------
__global__ __launch_bounds__(640) void nms_kernel(
    const float* __restrict__ roisall,   // [600][5]
    const float* __restrict__ scores,    // [600]
    float* __restrict__ out_keep)        // [300]
{
    __shared__ float s_sc[600];
    __shared__ int s_ord[600];
    __shared__ float bxs[600 * 4];
    __shared__ float s_area[600];
    __shared__ unsigned char s_kept[600];

    int t = threadIdx.x;
    if (t < 600) s_sc[t] = scores[t];
    __syncthreads();

    // stable descending argsort via rank counting
    if (t < 600) {
        float si = s_sc[t];
        int cnt = 0;
        for (int j = 0; j < 600; j++) {
            float sj = s_sc[j];
            cnt += (sj > si) || (sj == si && j < t);
        }
        s_ord[cnt] = t;
    }
    __syncthreads();

    float bx1 = 0.f, by1 = 0.f, bx2 = 0.f, by2 = 0.f, myArea = 0.f;
    bool kept_self = false;
    if (t < 600) {
        int o = s_ord[t];
        bx1 = roisall[(size_t)o * 5 + 1];
        by1 = roisall[(size_t)o * 5 + 2];
        bx2 = roisall[(size_t)o * 5 + 3];
        by2 = roisall[(size_t)o * 5 + 4];
        myArea = fmaxf(bx2 - bx1, 0.0f) * fmaxf(by2 - by1, 0.0f);
        bxs[t * 4 + 0] = bx1;
        bxs[t * 4 + 1] = by1;
        bxs[t * 4 + 2] = bx2;
        bxs[t * 4 + 3] = by2;
        s_area[t] = myArea;
    }
    __syncthreads();

    for (int i = 0; i < 600; i++) {
        bool p = false;
        if (t < i && kept_self) {
            float cx1 = bxs[i * 4 + 0], cy1 = bxs[i * 4 + 1];
            float cx2 = bxs[i * 4 + 2], cy2 = bxs[i * 4 + 3];
            float ix1 = fmaxf(cx1, bx1), iy1 = fmaxf(cy1, by1);
            float ix2 = fminf(cx2, bx2), iy2 = fminf(cy2, by2);
            float inter = fmaxf(ix2 - ix1, 0.0f) * fmaxf(iy2 - iy1, 0.0f);
            float denom = s_area[i] + myArea - inter + 1e-8f;
            float iou = __fdiv_rn(inter, denom);
            p = iou > 0.3f;
        }
        int any = __syncthreads_or((int)p);
        if (t == i) kept_self = !any;
    }

    if (t < 600) s_kept[t] = kept_self ? 1 : 0;
    __syncthreads();

    if (t == 0) {
        int rc = 0;
        for (int p2 = 0; p2 < 600 && rc < 300; p2++) {
            if (s_kept[p2]) out_keep[rc++] = (float)s_ord[p2];
        }
        for (; rc < 300; rc++) out_keep[rc] = -1.0f;
    }
}

// ---------------- launch ----------------------------------------------------------
extern "C" void kernel_launch(void* const* d_in, const int* in_sizes, int n_in,
                              void* d_out, int out_size)
{
    const float* feat = (const float*)d_in[0];   // [1,160,160,1024]
    const float* Wps  = (const float*)d_in[1];   // [1024,196]
    const float* bps  = (const float*)d_in[2];   // [196]
    const float* Wbb  = (const float*)d_in[3];   // [1024,196]
    const float* bbb  = (const float*)d_in[4];   // [196]
    const float* rois = (const float*)d_in[5];   // [300,5]

    float* out = (float*)d_out;
    float* o_cls  = out;            // 600*2   = 1200
    float* o_res  = out + 1200;     // 600
    float* o_sc   = out + 1800;     // 600
    float* o_mask = out + 2400;     // 600*14*14*2 = 235200
    float* o_ra   = out + 237600;   // 600*5 = 3000
    float* o_bb   = out + 240600;   // 600*4 = 2400
    float* o_keep = out + 243000;   // 300

    float *p_ps, *p_bb, *p_off, *p_ra, *p_sc;
    cudaGetSymbolAddress((void**)&p_ps, g_ps);
    cudaGetSymbolAddress((void**)&p_bb, g_bb);
    cudaGetSymbolAddress((void**)&p_off, g_off);
    cudaGetSymbolAddress((void**)&p_ra, g_roisall);
    cudaGetSymbolAddress((void**)&p_sc, g_scores);

    // 1. feature maps
    gemm_maps<<<dim3(200, 7), 256>>>(feat, Wps, bps, Wbb, bbb, p_ps, p_bb);
    // 2. offsets for the original 300 rois
    pooled4_kernel<<<300, 256>>>(rois, p_bb, p_off);
    // 3. proposals + rois_all (also writes d_out rois_all section)
    proposal_kernel<<<2, 256>>>(rois, p_off, p_ra, o_ra);
    // 4. bbox for all 600 rois
    pooled4_kernel<<<600, 256>>>(p_ra, p_bb, o_bb);
    // 5. cls / score / mask for all 600 rois
    cls_mask_kernel<<<600, 256>>>(p_ra, p_ps, o_cls, o_res, o_sc, o_mask, p_sc);
    // 6. NMS
    nms_kernel<<<1, 640>>>(p_ra, p_sc, o_keep);
}